// round 8
// baseline (speedup 1.0000x reference)
#include <cuda_runtime.h>

// MeanAggregator: out[b] = mean over DISTINCT sampled neighbors of features[nbrs[b,s]]
// features: float32 [N=200000, D=256]   (d_in[0])
// nbrs:     int32   [B=32768, S=10]     (d_in[1])
// out:      float32 [B, D]              (d_out)
//
// FINAL (converged at random-gather DRAM roofline, ~5.9-6.0 TB/s effective):
//  - 64 lanes per row, one float4 per (lane, sample): each feature row is
//    fetched as 8 fully-coalesced 128B lines; 10 independent loads/thread.
//  - __ldcg: L2-only caching (no reuse below L2).
//  - __stcs streaming stores (output never re-read).
//  - dedup via 45 int compares per thread (dups are ~2e-4 per row but
//    required for exactness); weights applied as FMA so all loads are
//    unconditional and independent.
// Levers tested and found neutral (DRAM-roofline-bound): MLP x2, occupancy
// 43->85%, LDG.256, STG.256, mask-based weights. Traffic is at its analytic
// floor (~255 MB); DRAM busy ~76% is the activate-overhead ceiling for
// uniform-random 1KB granules.

#define D 256
#define S 10
#define LANES 64
#define ROWS_PER_CTA 4

__global__ __launch_bounds__(LANES * ROWS_PER_CTA)
void mean_agg_kernel(const float* __restrict__ feat,
                     const int* __restrict__ nbrs,
                     float* __restrict__ out,
                     int B)
{
    const int row = blockIdx.x * ROWS_PER_CTA + threadIdx.y;   // grid exact
    const int lane = threadIdx.x;            // 0..63, owns floats [lane*4, lane*4+4)

    // Vectorized index load: 40 bytes per row, 8-byte aligned -> 5x int2.
    const int2* __restrict__ nb2 =
        reinterpret_cast<const int2*>(nbrs + (long long)row * S);
    int idx[S];
#pragma unroll
    for (int i = 0; i < 5; ++i) {
        int2 p = nb2[i];
        idx[2 * i]     = p.x;
        idx[2 * i + 1] = p.y;
    }

    // First-occurrence weights (dedup) + distinct count. O(S^2)=45 compares.
    float w[S];
    float n = 0.f;
#pragma unroll
    for (int i = 0; i < S; ++i) {
        bool dup = false;
#pragma unroll
        for (int j = 0; j < i; ++j) dup |= (idx[j] == idx[i]);
        w[i] = dup ? 0.f : 1.f;
        n += w[i];
    }

    // Unconditional weighted gathers (L2-only). 10 independent LDG.128 in
    // flight per thread, fully coalesced across the 64 lanes.
    float4 acc = make_float4(0.f, 0.f, 0.f, 0.f);
#pragma unroll
    for (int i = 0; i < S; ++i) {
        const float4 v = __ldcg(reinterpret_cast<const float4*>(
            feat + (long long)idx[i] * D + lane * 4));
        acc.x = fmaf(w[i], v.x, acc.x);
        acc.y = fmaf(w[i], v.y, acc.y);
        acc.z = fmaf(w[i], v.z, acc.z);
        acc.w = fmaf(w[i], v.w, acc.w);
    }

    const float inv = 1.f / n;
    float4 o;
    o.x = acc.x * inv;
    o.y = acc.y * inv;
    o.z = acc.z * inv;
    o.w = acc.w * inv;

    // Streaming store: output never re-read; keep L2 capacity for features.
    __stcs(reinterpret_cast<float4*>(out + (long long)row * D + lane * 4), o);
}

extern "C" void kernel_launch(void* const* d_in, const int* in_sizes, int n_in,
                              void* d_out, int out_size)
{
    const float* feat = (const float*)d_in[0];
    const int*   nbrs = (const int*)d_in[1];
    float*       out  = (float*)d_out;

    const int B = in_sizes[1] / S;           // 32768

    dim3 block(LANES, ROWS_PER_CTA);
    dim3 grid(B / ROWS_PER_CTA);
    mean_agg_kernel<<<grid, block>>>(feat, nbrs, out, B);
}

// round 9
// speedup vs baseline: 1.0896x; 1.0896x over previous
#include <cuda_runtime.h>

// MeanAggregator: out[b] = mean over DISTINCT sampled neighbors of features[nbrs[b,s]]
// features: float32 [N=200000, D=256]   (d_in[0])
// nbrs:     int32   [B=32768, S=10]     (d_in[1])
// out:      float32 [B, D]              (d_out)
//
// FINAL — exact replica of the best-measured variant (R3: 42.91us bench).
// Converged at the random-gather DRAM roofline (~250 MB irreducible traffic,
// ~75% DRAM busy = activate-overhead ceiling for uniform-random 1KB rows).
// Levers tested and neutral within the +/-3% noise band: L1 bypass already
// in, streaming stores, per-thread MLP x2, occupancy 43->85%, LDG.256,
// STG.256, mask-based weights.

#define D 256
#define S 10
#define LANES 64
#define ROWS_PER_CTA 4

__global__ __launch_bounds__(LANES * ROWS_PER_CTA)
void mean_agg_kernel(const float* __restrict__ feat,
                     const int* __restrict__ nbrs,
                     float* __restrict__ out,
                     int B)
{
    const int row = blockIdx.x * ROWS_PER_CTA + threadIdx.y;
    if (row >= B) return;
    const int lane = threadIdx.x;            // 0..63, owns floats [lane*4, lane*4+4)

    // Vectorized index load: 40 bytes per row, 8-byte aligned -> 5x int2.
    const int2* __restrict__ nb2 =
        reinterpret_cast<const int2*>(nbrs + (long long)row * S);
    int idx[S];
#pragma unroll
    for (int i = 0; i < 5; ++i) {
        int2 p = nb2[i];
        idx[2 * i]     = p.x;
        idx[2 * i + 1] = p.y;
    }

    // First-occurrence weights (dedup) + distinct count. O(S^2)=45 compares.
    float w[S];
    float n = 0.f;
#pragma unroll
    for (int i = 0; i < S; ++i) {
        bool dup = false;
#pragma unroll
        for (int j = 0; j < i; ++j) dup |= (idx[j] == idx[i]);
        w[i] = dup ? 0.f : 1.f;
        n += w[i];
    }

    // Unconditional weighted gathers. __ldcg: cache in L2 only — each 128B
    // line is consumed by exactly one warp, so L1 allocation is pure waste;
    // cross-row reuse lives in L2.
    float4 acc = make_float4(0.f, 0.f, 0.f, 0.f);
#pragma unroll
    for (int i = 0; i < S; ++i) {
        const float4 v = __ldcg(reinterpret_cast<const float4*>(
            feat + (long long)idx[i] * D + lane * 4));
        acc.x += w[i] * v.x;
        acc.y += w[i] * v.y;
        acc.z += w[i] * v.z;
        acc.w += w[i] * v.w;
    }

    const float inv = 1.f / n;
    float4 o;
    o.x = acc.x * inv;
    o.y = acc.y * inv;
    o.z = acc.z * inv;
    o.w = acc.w * inv;

    // Streaming store: output is never re-read; evict-first keeps L2
    // capacity for feature-row reuse.
    __stcs(reinterpret_cast<float4*>(out + (long long)row * D + lane * 4), o);
}

extern "C" void kernel_launch(void* const* d_in, const int* in_sizes, int n_in,
                              void* d_out, int out_size)
{
    const float* feat = (const float*)d_in[0];
    const int*   nbrs = (const int*)d_in[1];
    float*       out  = (float*)d_out;

    const int B = in_sizes[1] / S;           // 32768

    dim3 block(LANES, ROWS_PER_CTA);
    dim3 grid((B + ROWS_PER_CTA - 1) / ROWS_PER_CTA);
    mean_agg_kernel<<<grid, block>>>(feat, nbrs, out, B);
}